// round 7
// baseline (speedup 1.0000x reference)
#include <cuda_runtime.h>
#include <cstdint>
#include <math.h>

// ---------------- problem constants ----------------
#define NUM_E 8
#define M_TOK 2048
#define H_DIM 1024
#define I_DIM 4096

// Intermediate activations: [E, 2048, 4096] fp32 = 256MB static scratch
__device__ float g_act[(size_t)NUM_E * M_TOK * I_DIM];

// ---------------- tile config ----------------
#define BM 128
#define BN 128
#define BK 32
#define STAGES 3
#define ASTR 36    // (36*grp + qid) % 32 == (4*grp+qid) -> distinct for grp<8,qid<4
#define BSTR 136   // (136*qid + grp) % 32 == (8*qid+grp) -> distinct for qid<4,grp<8
#define A_WORDS (BM * ASTR)            // 4608 words
#define B_WORDS (BK * BSTR)            // 4352 words
#define STAGE_WORDS (A_WORDS + B_WORDS)  // 8960 words = 35840 B
#define SMEM_BYTES (STAGES * STAGE_WORDS * 4)  // 107520 B -> 2 CTAs/SM

__device__ __forceinline__ uint32_t cvt_tf32(float f) {
    uint32_t u;
    asm volatile("cvt.rna.tf32.f32 %0, %1;" : "=r"(u) : "f"(f));
    return u;
}
__device__ __forceinline__ void cp_async16(uint32_t smem, const void* gmem) {
    asm volatile("cp.async.cg.shared.global [%0], [%1], 16;\n" :: "r"(smem), "l"(gmem));
}
__device__ __forceinline__ void cp_commit() { asm volatile("cp.async.commit_group;\n" ::: "memory"); }
template <int N> __device__ __forceinline__ void cp_wait() {
    asm volatile("cp.async.wait_group %0;\n" :: "n"(N) : "memory");
}
__device__ __forceinline__ float gelu_exact(float v) {
    return 0.5f * v * (1.0f + erff(v * 0.70710678118654752440f));
}

// D = A @ B (+ optional exact GELU).
// A: [Mdim, Kdim] row-major per expert.  B: [Kdim, Ndim] row-major per expert (native wi/wo layout).
template <bool GELU>
__global__ void __launch_bounds__(128) gemm_tf32_v2(
    const float* __restrict__ Aall, const float* __restrict__ Ball, float* __restrict__ Dall,
    int Mdim, int Ndim, int Kdim)
{
    extern __shared__ float smem[];

    const int e = blockIdx.z;
    const float* A = Aall + (size_t)e * Mdim * Kdim + (size_t)blockIdx.y * BM * Kdim;
    const float* B = Ball + (size_t)e * Kdim * Ndim + (size_t)blockIdx.x * BN;
    float* D = Dall + (size_t)e * Mdim * Ndim + (size_t)blockIdx.y * BM * Ndim + blockIdx.x * BN;

    const int tid = threadIdx.x;
    const int warp = tid >> 5;
    const int lane = tid & 31;
    const int wm = warp >> 1;   // 0..1 -> 64-row band
    const int wn = warp & 1;    // 0..1 -> 64-col band
    const int grp = lane >> 2;  // 0..7
    const int qid = lane & 3;   // 0..3

    const int KT = Kdim / BK;

    auto issue_loads = [&](int chunk) {
        float* s = smem + (size_t)(chunk % STAGES) * STAGE_WORDS;
        const float* Ac = A + chunk * BK;
        const float* Bc = B + (size_t)chunk * BK * Ndim;
        // A tile: 128 rows x 8 16B-chunks = 1024 chunks -> 8 per thread
        #pragma unroll
        for (int i = 0; i < 8; ++i) {
            int idx = tid + 128 * i;
            int row = idx >> 3, k0 = (idx & 7) << 2;
            uint32_t dst = (uint32_t)__cvta_generic_to_shared(s + row * ASTR + k0);
            cp_async16(dst, Ac + (size_t)row * Kdim + k0);
        }
        // B tile: 32 rows x 32 16B-chunks = 1024 chunks -> 8 per thread
        float* sb = s + A_WORDS;
        #pragma unroll
        for (int i = 0; i < 8; ++i) {
            int idx = tid + 128 * i;
            int k = idx >> 5, n0 = (idx & 31) << 2;
            uint32_t dst = (uint32_t)__cvta_generic_to_shared(sb + k * BSTR + n0);
            cp_async16(dst, Bc + (size_t)k * Ndim + n0);
        }
    };

    float acc[4][8][4];
    #pragma unroll
    for (int a = 0; a < 4; a++)
        #pragma unroll
        for (int b = 0; b < 8; b++)
            #pragma unroll
            for (int c = 0; c < 4; c++) acc[a][b][c] = 0.f;

    issue_loads(0); cp_commit();
    issue_loads(1); cp_commit();

    for (int kt = 0; kt < KT; ++kt) {
        cp_wait<1>();        // stage kt's fill complete
        __syncthreads();     // also: all warps done reading stage (kt-1) -> safe to overwrite
        if (kt + 2 < KT) issue_loads(kt + 2);
        cp_commit();         // exactly one group per iter keeps wait<1> exact

        const float* cA = smem + (size_t)(kt % STAGES) * STAGE_WORDS;
        const float* cB = cA + A_WORDS;

        #pragma unroll
        for (int ks = 0; ks < 4; ++ks) {
            const int kk = ks * 8;
            uint32_t af[4][4], bf[8][2];
            #pragma unroll
            for (int mt = 0; mt < 4; ++mt) {
                int r = wm * 64 + mt * 16 + grp;
                af[mt][0] = cvt_tf32(cA[r * ASTR + kk + qid]);
                af[mt][1] = cvt_tf32(cA[(r + 8) * ASTR + kk + qid]);
                af[mt][2] = cvt_tf32(cA[r * ASTR + kk + qid + 4]);
                af[mt][3] = cvt_tf32(cA[(r + 8) * ASTR + kk + qid + 4]);
            }
            #pragma unroll
            for (int nt = 0; nt < 8; ++nt) {
                int cc = wn * 64 + nt * 8 + grp;
                bf[nt][0] = cvt_tf32(cB[(kk + qid) * BSTR + cc]);
                bf[nt][1] = cvt_tf32(cB[(kk + qid + 4) * BSTR + cc]);
            }
            #pragma unroll
            for (int mt = 0; mt < 4; ++mt)
                #pragma unroll
                for (int nt = 0; nt < 8; ++nt) {
                    asm volatile(
                        "mma.sync.aligned.m16n8k8.row.col.f32.tf32.tf32.f32 "
                        "{%0,%1,%2,%3}, {%4,%5,%6,%7}, {%8,%9}, {%0,%1,%2,%3};\n"
                        : "+f"(acc[mt][nt][0]), "+f"(acc[mt][nt][1]),
                          "+f"(acc[mt][nt][2]), "+f"(acc[mt][nt][3])
                        : "r"(af[mt][0]), "r"(af[mt][1]), "r"(af[mt][2]), "r"(af[mt][3]),
                          "r"(bf[nt][0]), "r"(bf[nt][1]));
                }
        }
    }

    // Epilogue. C fragment: c0:(grp,2q) c1:(grp,2q+1) c2:(grp+8,2q) c3:(grp+8,2q+1)
    #pragma unroll
    for (int mt = 0; mt < 4; ++mt) {
        int r = wm * 64 + mt * 16 + grp;
        #pragma unroll
        for (int nt = 0; nt < 8; ++nt) {
            int c = wn * 64 + nt * 8 + 2 * qid;
            float v0 = acc[mt][nt][0], v1 = acc[mt][nt][1];
            float v2 = acc[mt][nt][2], v3 = acc[mt][nt][3];
            if (GELU) {
                v0 = gelu_exact(v0); v1 = gelu_exact(v1);
                v2 = gelu_exact(v2); v3 = gelu_exact(v3);
            }
            *(float2*)(&D[(size_t)r * Ndim + c])       = make_float2(v0, v1);
            *(float2*)(&D[(size_t)(r + 8) * Ndim + c]) = make_float2(v2, v3);
        }
    }
}

extern "C" void kernel_launch(void* const* d_in, const int* in_sizes, int n_in,
                              void* d_out, int out_size) {
    const float* x  = (const float*)d_in[0];   // [8, 2048, 1024]
    const float* wi = (const float*)d_in[1];   // [8, 1024, 4096]  == [K, N] per expert
    const float* wo = (const float*)d_in[2];   // [8, 4096, 1024]  == [K, N] per expert
    float* out = (float*)d_out;                // [8, 2048, 1024]

    float* act;
    cudaGetSymbolAddress((void**)&act, g_act);

    cudaFuncSetAttribute(gemm_tf32_v2<true>,  cudaFuncAttributeMaxDynamicSharedMemorySize, SMEM_BYTES);
    cudaFuncSetAttribute(gemm_tf32_v2<false>, cudaFuncAttributeMaxDynamicSharedMemorySize, SMEM_BYTES);

    // GEMM1: act = gelu(x @ wi)   M=2048 N=4096 K=1024
    gemm_tf32_v2<true><<<dim3(I_DIM / BN, M_TOK / BM, NUM_E), 128, SMEM_BYTES>>>(
        x, wi, act, M_TOK, I_DIM, H_DIM);
    // GEMM2: out = act @ wo       M=2048 N=1024 K=4096
    gemm_tf32_v2<false><<<dim3(H_DIM / BN, M_TOK / BM, NUM_E), 128, SMEM_BYTES>>>(
        act, wo, out, M_TOK, H_DIM, I_DIM);
}

// round 10
// speedup vs baseline: 1.9438x; 1.9438x over previous
#include <cuda_runtime.h>
#include <cuda_fp16.h>
#include <cstdint>
#include <math.h>

// ---------------- problem constants ----------------
#define NUM_E 8
#define M_TOK 2048
#define H_DIM 1024
#define I_DIM 4096

// ---------------- fp16 scratch (no allocs allowed) ----------------
__device__ __half g_xh [(size_t)NUM_E * M_TOK * H_DIM];   //  32 MB
__device__ __half g_wih[(size_t)NUM_E * H_DIM * I_DIM];   //  64 MB
__device__ __half g_woh[(size_t)NUM_E * I_DIM * H_DIM];   //  64 MB
__device__ __half g_act[(size_t)NUM_E * M_TOK * I_DIM];   // 128 MB

// ---------------- tile config ----------------
#define BM 128
#define BN 128
#define BK 64               // 64 fp16 elements per stage along K
#define STAGES 3
#define ASTR 72             // halves; 144B rows -> ldmatrix rows start banks 4r mod 32 (disjoint)
#define BSTR 136            // halves; 272B rows -> banks 4k mod 32 (disjoint)
#define A_HALVES (BM * ASTR)              // 9216
#define B_HALVES (BK * BSTR)              // 8704
#define STAGE_HALVES (A_HALVES + B_HALVES)  // 17920 halves = 35840 B
#define SMEM_BYTES (STAGES * STAGE_HALVES * 2)   // 107520 B -> 2 CTAs/SM

__device__ __forceinline__ void cp_async16(uint32_t smem, const void* gmem) {
    asm volatile("cp.async.cg.shared.global [%0], [%1], 16;\n" :: "r"(smem), "l"(gmem));
}
__device__ __forceinline__ void cp_commit() { asm volatile("cp.async.commit_group;\n" ::: "memory"); }
template <int N> __device__ __forceinline__ void cp_wait() {
    asm volatile("cp.async.wait_group %0;\n" :: "n"(N) : "memory");
}
__device__ __forceinline__ void ldsm_x4(uint32_t& r0, uint32_t& r1, uint32_t& r2, uint32_t& r3,
                                        uint32_t addr) {
    asm volatile("ldmatrix.sync.aligned.m8n8.x4.shared.b16 {%0,%1,%2,%3}, [%4];"
                 : "=r"(r0), "=r"(r1), "=r"(r2), "=r"(r3) : "r"(addr));
}
__device__ __forceinline__ void ldsm_x4_t(uint32_t& r0, uint32_t& r1, uint32_t& r2, uint32_t& r3,
                                          uint32_t addr) {
    asm volatile("ldmatrix.sync.aligned.m8n8.x4.trans.shared.b16 {%0,%1,%2,%3}, [%4];"
                 : "=r"(r0), "=r"(r1), "=r"(r2), "=r"(r3) : "r"(addr));
}
__device__ __forceinline__ float gelu_exact(float v) {
    return 0.5f * v * (1.0f + erff(v * 0.70710678118654752440f));
}

// ---------------- fp32 -> fp16 conversion ----------------
__global__ void __launch_bounds__(256) cvt_f32_f16(const float* __restrict__ in,
                                                   __half* __restrict__ out, size_t n4) {
    size_t i = (size_t)blockIdx.x * blockDim.x + threadIdx.x;
    size_t stride = (size_t)gridDim.x * blockDim.x;
    const float4* in4 = (const float4*)in;
    uint2* out4 = (uint2*)out;   // 4 halves
    for (; i < n4; i += stride) {
        float4 v = in4[i];
        __half2 lo = __float22half2_rn(make_float2(v.x, v.y));
        __half2 hi = __float22half2_rn(make_float2(v.z, v.w));
        uint2 o;
        o.x = *(uint32_t*)&lo;
        o.y = *(uint32_t*)&hi;
        out4[i] = o;
    }
}

// ---------------- fp16 GEMM ----------------
// A: [Mdim, Kdim] fp16 row-major per expert.  B: [Kdim, Ndim] fp16 row-major per expert.
// GELU=true: D is fp16 (activations).  GELU=false: D is fp32 (final output).
template <bool GELU>
__global__ void __launch_bounds__(128) gemm_f16(
    const __half* __restrict__ Aall, const __half* __restrict__ Ball, void* __restrict__ Dall,
    int Mdim, int Ndim, int Kdim)
{
    extern __shared__ __half smem[];
    const uint32_t smem_base = (uint32_t)__cvta_generic_to_shared(smem);

    const int e = blockIdx.z;
    const __half* A = Aall + (size_t)e * Mdim * Kdim + (size_t)blockIdx.y * BM * Kdim;
    const __half* B = Ball + (size_t)e * Kdim * Ndim + (size_t)blockIdx.x * BN;

    const int tid = threadIdx.x;
    const int warp = tid >> 5;
    const int lane = tid & 31;
    const int wm = warp >> 1;      // 0..1 -> 64-row band
    const int wn = warp & 1;       // 0..1 -> 64-col band
    const int grp = lane >> 2;     // 0..7
    const int qid = lane & 3;      // 0..3

    const int KT = Kdim / BK;

    auto issue_loads = [&](int chunk) {
        uint32_t s = smem_base + (uint32_t)(chunk % STAGES) * (STAGE_HALVES * 2);
        const __half* Ac = A + chunk * BK;
        const __half* Bc = B + (size_t)chunk * BK * Ndim;
        // A tile: 128 rows x 8 chunks of 8 halves (16B) -> 8 per thread
        #pragma unroll
        for (int i = 0; i < 8; ++i) {
            int idx = tid + 128 * i;
            int row = idx >> 3, c8 = idx & 7;
            cp_async16(s + (uint32_t)row * (ASTR * 2) + (uint32_t)c8 * 16,
                       Ac + (size_t)row * Kdim + c8 * 8);
        }
        // B tile: 64 k-rows x 16 chunks -> 8 per thread
        uint32_t sb = s + A_HALVES * 2;
        #pragma unroll
        for (int i = 0; i < 8; ++i) {
            int idx = tid + 128 * i;
            int k = idx >> 4, c8 = idx & 15;
            cp_async16(sb + (uint32_t)k * (BSTR * 2) + (uint32_t)c8 * 16,
                       Bc + (size_t)k * Ndim + c8 * 8);
        }
    };

    float acc[4][8][4];
    #pragma unroll
    for (int a = 0; a < 4; a++)
        #pragma unroll
        for (int b = 0; b < 8; b++)
            #pragma unroll
            for (int c = 0; c < 4; c++) acc[a][b][c] = 0.f;

    // ldmatrix lane addressing components
    const int lrow = lane & 15;         // row within 16
    const int lcol8 = (lane >> 4) * 8;  // 0 or 8 halves

    issue_loads(0); cp_commit();
    issue_loads(1); cp_commit();

    for (int kt = 0; kt < KT; ++kt) {
        cp_wait<1>();
        __syncthreads();
        if (kt + 2 < KT) issue_loads(kt + 2);
        cp_commit();     // exactly one group per iteration keeps wait<1> exact

        uint32_t s = smem_base + (uint32_t)(kt % STAGES) * (STAGE_HALVES * 2);
        uint32_t sb = s + A_HALVES * 2;

        #pragma unroll
        for (int ks = 0; ks < 4; ++ks) {       // 4 x k16 steps
            const int k0 = ks * 16;
            uint32_t af[4][4], bf[8][2];
            // A fragments: 4 ldmatrix.x4 (rows m, cols k)
            #pragma unroll
            for (int mt = 0; mt < 4; ++mt) {
                int r = wm * 64 + mt * 16 + lrow;
                uint32_t addr = s + (uint32_t)r * (ASTR * 2) + (uint32_t)(k0 + lcol8) * 2;
                ldsm_x4(af[mt][0], af[mt][1], af[mt][2], af[mt][3], addr);
            }
            // B fragments: 4 ldmatrix.x4.trans, each covers two n-blocks of 8
            #pragma unroll
            for (int np = 0; np < 4; ++np) {
                int krow = k0 + lrow;
                int c = wn * 64 + np * 16 + lcol8;
                uint32_t addr = sb + (uint32_t)krow * (BSTR * 2) + (uint32_t)c * 2;
                ldsm_x4_t(bf[np * 2][0], bf[np * 2][1], bf[np * 2 + 1][0], bf[np * 2 + 1][1], addr);
            }
            #pragma unroll
            for (int mt = 0; mt < 4; ++mt)
                #pragma unroll
                for (int nt = 0; nt < 8; ++nt) {
                    asm volatile(
                        "mma.sync.aligned.m16n8k16.row.col.f32.f16.f16.f32 "
                        "{%0,%1,%2,%3}, {%4,%5,%6,%7}, {%8,%9}, {%0,%1,%2,%3};\n"
                        : "+f"(acc[mt][nt][0]), "+f"(acc[mt][nt][1]),
                          "+f"(acc[mt][nt][2]), "+f"(acc[mt][nt][3])
                        : "r"(af[mt][0]), "r"(af[mt][1]), "r"(af[mt][2]), "r"(af[mt][3]),
                          "r"(bf[nt][0]), "r"(bf[nt][1]));
                }
        }
    }

    // Epilogue. C fragment: c0:(grp,2q) c1:(grp,2q+1) c2:(grp+8,2q) c3:(grp+8,2q+1)
    if (GELU) {
        __half* D = (__half*)Dall + (size_t)e * Mdim * Ndim
                  + (size_t)blockIdx.y * BM * Ndim + blockIdx.x * BN;
        #pragma unroll
        for (int mt = 0; mt < 4; ++mt) {
            int r = wm * 64 + mt * 16 + grp;
            #pragma unroll
            for (int nt = 0; nt < 8; ++nt) {
                int c = wn * 64 + nt * 8 + 2 * qid;
                __half2 h0 = __float22half2_rn(make_float2(gelu_exact(acc[mt][nt][0]),
                                                           gelu_exact(acc[mt][nt][1])));
                __half2 h1 = __float22half2_rn(make_float2(gelu_exact(acc[mt][nt][2]),
                                                           gelu_exact(acc[mt][nt][3])));
                *(__half2*)(&D[(size_t)r * Ndim + c])       = h0;
                *(__half2*)(&D[(size_t)(r + 8) * Ndim + c]) = h1;
            }
        }
    } else {
        float* D = (float*)Dall + (size_t)e * Mdim * Ndim
                 + (size_t)blockIdx.y * BM * Ndim + blockIdx.x * BN;
        #pragma unroll
        for (int mt = 0; mt < 4; ++mt) {
            int r = wm * 64 + mt * 16 + grp;
            #pragma unroll
            for (int nt = 0; nt < 8; ++nt) {
                int c = wn * 64 + nt * 8 + 2 * qid;
                *(float2*)(&D[(size_t)r * Ndim + c]) =
                    make_float2(acc[mt][nt][0], acc[mt][nt][1]);
                *(float2*)(&D[(size_t)(r + 8) * Ndim + c]) =
                    make_float2(acc[mt][nt][2], acc[mt][nt][3]);
            }
        }
    }
}

extern "C" void kernel_launch(void* const* d_in, const int* in_sizes, int n_in,
                              void* d_out, int out_size) {
    const float* x  = (const float*)d_in[0];   // [8, 2048, 1024]
    const float* wi = (const float*)d_in[1];   // [8, 1024, 4096]  (= [K,N] per expert)
    const float* wo = (const float*)d_in[2];   // [8, 4096, 1024]  (= [K,N] per expert)
    float* out = (float*)d_out;                // [8, 2048, 1024] fp32

    __half *xh, *wih, *woh, *act;
    cudaGetSymbolAddress((void**)&xh,  g_xh);
    cudaGetSymbolAddress((void**)&wih, g_wih);
    cudaGetSymbolAddress((void**)&woh, g_woh);
    cudaGetSymbolAddress((void**)&act, g_act);

    cudaFuncSetAttribute(gemm_f16<true>,  cudaFuncAttributeMaxDynamicSharedMemorySize, SMEM_BYTES);
    cudaFuncSetAttribute(gemm_f16<false>, cudaFuncAttributeMaxDynamicSharedMemorySize, SMEM_BYTES);

    // fp32 -> fp16 conversions
    const size_t nx  = (size_t)NUM_E * M_TOK * H_DIM;
    const size_t nwi = (size_t)NUM_E * H_DIM * I_DIM;
    const size_t nwo = (size_t)NUM_E * I_DIM * H_DIM;
    cvt_f32_f16<<<1184, 256>>>(x,  xh,  nx  / 4);
    cvt_f32_f16<<<1184, 256>>>(wi, wih, nwi / 4);
    cvt_f32_f16<<<1184, 256>>>(wo, woh, nwo / 4);

    // GEMM1: act = gelu(x @ wi)   M=2048 N=4096 K=1024  (fp16 out)
    gemm_f16<true><<<dim3(I_DIM / BN, M_TOK / BM, NUM_E), 128, SMEM_BYTES>>>(
        xh, wih, act, M_TOK, I_DIM, H_DIM);
    // GEMM2: out = act @ wo       M=2048 N=1024 K=4096  (fp32 out)
    gemm_f16<false><<<dim3(H_DIM / BN, M_TOK / BM, NUM_E), 128, SMEM_BYTES>>>(
        act, woh, out, M_TOK, H_DIM, I_DIM);
}

// round 13
// speedup vs baseline: 1.9682x; 1.0125x over previous
#include <cuda_runtime.h>
#include <cuda_fp16.h>
#include <cstdint>
#include <math.h>

// ---------------- problem constants ----------------
#define NUM_E 8
#define M_TOK 2048
#define H_DIM 1024
#define I_DIM 4096

// ---------------- fp16 scratch (no allocs allowed) ----------------
__device__ __half g_xh [(size_t)NUM_E * M_TOK * H_DIM];   //  32 MB
__device__ __half g_wih[(size_t)NUM_E * H_DIM * I_DIM];   //  64 MB
__device__ __half g_woh[(size_t)NUM_E * I_DIM * H_DIM];   //  64 MB
__device__ __half g_act[(size_t)NUM_E * M_TOK * I_DIM];   // 128 MB

// ---------------- tile config ----------------
#define BM 128
#define BN 128
#define BK 64
#define STAGES 3
#define ASTR 72             // halves; 144B rows -> ldsm rows hit banks 4r mod 32 (disjoint per phase)
#define BSTR 136            // halves; 272B rows -> banks 4k mod 32 (disjoint per phase)
#define A_HALVES (BM * ASTR)                 // 9216
#define B_HALVES (BK * BSTR)                 // 8704
#define STAGE_HALVES (A_HALVES + B_HALVES)   // 17920 halves = 35840 B
#define SMEM_BYTES (STAGES * STAGE_HALVES * 2)  // 107520 B/CTA -> 2 CTAs/SM (215KB)

__device__ __forceinline__ void cp_async16(uint32_t smem, const void* gmem) {
    asm volatile("cp.async.cg.shared.global [%0], [%1], 16;\n" :: "r"(smem), "l"(gmem));
}
__device__ __forceinline__ void cp_commit() { asm volatile("cp.async.commit_group;\n" ::: "memory"); }
template <int N> __device__ __forceinline__ void cp_wait() {
    asm volatile("cp.async.wait_group %0;\n" :: "n"(N) : "memory");
}
__device__ __forceinline__ void ldsm_x4(uint32_t& r0, uint32_t& r1, uint32_t& r2, uint32_t& r3,
                                        uint32_t addr) {
    asm volatile("ldmatrix.sync.aligned.m8n8.x4.shared.b16 {%0,%1,%2,%3}, [%4];"
                 : "=r"(r0), "=r"(r1), "=r"(r2), "=r"(r3) : "r"(addr));
}
__device__ __forceinline__ void ldsm_x4_t(uint32_t& r0, uint32_t& r1, uint32_t& r2, uint32_t& r3,
                                          uint32_t addr) {
    asm volatile("ldmatrix.sync.aligned.m8n8.x4.trans.shared.b16 {%0,%1,%2,%3}, [%4];"
                 : "=r"(r0), "=r"(r1), "=r"(r2), "=r"(r3) : "r"(addr));
}
__device__ __forceinline__ float gelu_exact(float v) {
    return 0.5f * v * (1.0f + erff(v * 0.70710678118654752440f));
}

// ---------------- fp32 -> fp16 conversion ----------------
__global__ void __launch_bounds__(256) cvt_f32_f16(const float* __restrict__ in,
                                                   __half* __restrict__ out, size_t n4) {
    size_t i = (size_t)blockIdx.x * blockDim.x + threadIdx.x;
    size_t stride = (size_t)gridDim.x * blockDim.x;
    const float4* in4 = (const float4*)in;
    uint2* out4 = (uint2*)out;
    for (; i < n4; i += stride) {
        float4 v = in4[i];
        __half2 lo = __float22half2_rn(make_float2(v.x, v.y));
        __half2 hi = __float22half2_rn(make_float2(v.z, v.w));
        uint2 o;
        o.x = *(uint32_t*)&lo;
        o.y = *(uint32_t*)&hi;
        out4[i] = o;
    }
}

// ---------------- fp16 GEMM: 256 threads, 8 warps (2x4), warp tile 64x32 ----------------
// A: [Mdim, Kdim] fp16 row-major per expert.  B: [Kdim, Ndim] fp16 row-major per expert.
// GELU=true: D fp16 (activations).  GELU=false: D fp32 (final output).
template <bool GELU>
__global__ void __launch_bounds__(256, 2) gemm_f16_w8(
    const __half* __restrict__ Aall, const __half* __restrict__ Ball, void* __restrict__ Dall,
    int Mdim, int Ndim, int Kdim)
{
    extern __shared__ __half smem[];
    const uint32_t smem_base = (uint32_t)__cvta_generic_to_shared(smem);

    const int e = blockIdx.z;
    const __half* A = Aall + (size_t)e * Mdim * Kdim + (size_t)blockIdx.y * BM * Kdim;
    const __half* B = Ball + (size_t)e * Kdim * Ndim + (size_t)blockIdx.x * BN;

    const int tid = threadIdx.x;
    const int warp = tid >> 5;
    const int lane = tid & 31;
    const int wm = warp >> 2;      // 0..1 -> 64-row band
    const int wn = warp & 3;       // 0..3 -> 32-col band
    const int grp = lane >> 2;     // 0..7
    const int qid = lane & 3;      // 0..3
    const int lrow = lane & 15;
    const int lcol8 = (lane >> 4) * 8;

    const int KT = Kdim / BK;

    auto issue_loads = [&](int chunk) {
        uint32_t s = smem_base + (uint32_t)(chunk % STAGES) * (STAGE_HALVES * 2);
        const __half* Ac = A + chunk * BK;
        const __half* Bc = B + (size_t)chunk * BK * Ndim;
        // A tile: 128 rows x 8 chunks of 16B = 1024 -> 4 per thread
        #pragma unroll
        for (int i = 0; i < 4; ++i) {
            int idx = tid + 256 * i;
            int row = idx >> 3, c8 = idx & 7;
            cp_async16(s + (uint32_t)row * (ASTR * 2) + (uint32_t)c8 * 16,
                       Ac + (size_t)row * Kdim + c8 * 8);
        }
        // B tile: 64 k-rows x 16 chunks = 1024 -> 4 per thread
        uint32_t sb = s + A_HALVES * 2;
        #pragma unroll
        for (int i = 0; i < 4; ++i) {
            int idx = tid + 256 * i;
            int k = idx >> 4, c8 = idx & 15;
            cp_async16(sb + (uint32_t)k * (BSTR * 2) + (uint32_t)c8 * 16,
                       Bc + (size_t)k * Ndim + c8 * 8);
        }
    };

    float acc[4][4][4];
    #pragma unroll
    for (int a = 0; a < 4; a++)
        #pragma unroll
        for (int b = 0; b < 4; b++)
            #pragma unroll
            for (int c = 0; c < 4; c++) acc[a][b][c] = 0.f;

    issue_loads(0); cp_commit();
    issue_loads(1); cp_commit();

    for (int kt = 0; kt < KT; ++kt) {
        cp_wait<1>();
        __syncthreads();
        if (kt + 2 < KT) issue_loads(kt + 2);
        cp_commit();   // exactly one group per iteration keeps wait<1> exact

        uint32_t s = smem_base + (uint32_t)(kt % STAGES) * (STAGE_HALVES * 2);
        uint32_t sb = s + A_HALVES * 2;

        #pragma unroll
        for (int ks = 0; ks < 4; ++ks) {     // 4 x k16 steps
            const int k0 = ks * 16;
            uint32_t af[4][4], bf[4][2];
            // A fragments: 4 ldmatrix.x4 over m64 x k16
            #pragma unroll
            for (int mt = 0; mt < 4; ++mt) {
                int r = wm * 64 + mt * 16 + lrow;
                uint32_t addr = s + (uint32_t)r * (ASTR * 2) + (uint32_t)(k0 + lcol8) * 2;
                ldsm_x4(af[mt][0], af[mt][1], af[mt][2], af[mt][3], addr);
            }
            // B fragments: 2 ldmatrix.x4.trans over k16 x n32
            #pragma unroll
            for (int np = 0; np < 2; ++np) {
                int krow = k0 + lrow;
                int c = wn * 32 + np * 16 + lcol8;
                uint32_t addr = sb + (uint32_t)krow * (BSTR * 2) + (uint32_t)c * 2;
                ldsm_x4_t(bf[np * 2][0], bf[np * 2][1], bf[np * 2 + 1][0], bf[np * 2 + 1][1], addr);
            }
            #pragma unroll
            for (int mt = 0; mt < 4; ++mt)
                #pragma unroll
                for (int nt = 0; nt < 4; ++nt) {
                    asm volatile(
                        "mma.sync.aligned.m16n8k16.row.col.f32.f16.f16.f32 "
                        "{%0,%1,%2,%3}, {%4,%5,%6,%7}, {%8,%9}, {%0,%1,%2,%3};\n"
                        : "+f"(acc[mt][nt][0]), "+f"(acc[mt][nt][1]),
                          "+f"(acc[mt][nt][2]), "+f"(acc[mt][nt][3])
                        : "r"(af[mt][0]), "r"(af[mt][1]), "r"(af[mt][2]), "r"(af[mt][3]),
                          "r"(bf[nt][0]), "r"(bf[nt][1]));
                }
        }
    }

    // Epilogue. C fragment: c0:(grp,2q) c1:(grp,2q+1) c2:(grp+8,2q) c3:(grp+8,2q+1)
    if (GELU) {
        __half* D = (__half*)Dall + (size_t)e * Mdim * Ndim
                  + (size_t)blockIdx.y * BM * Ndim + blockIdx.x * BN;
        #pragma unroll
        for (int mt = 0; mt < 4; ++mt) {
            int r = wm * 64 + mt * 16 + grp;
            #pragma unroll
            for (int nt = 0; nt < 4; ++nt) {
                int c = wn * 32 + nt * 8 + 2 * qid;
                __half2 h0 = __float22half2_rn(make_float2(gelu_exact(acc[mt][nt][0]),
                                                           gelu_exact(acc[mt][nt][1])));
                __half2 h1 = __float22half2_rn(make_float2(gelu_exact(acc[mt][nt][2]),
                                                           gelu_exact(acc[mt][nt][3])));
                *(__half2*)(&D[(size_t)r * Ndim + c])       = h0;
                *(__half2*)(&D[(size_t)(r + 8) * Ndim + c]) = h1;
            }
        }
    } else {
        float* D = (float*)Dall + (size_t)e * Mdim * Ndim
                 + (size_t)blockIdx.y * BM * Ndim + blockIdx.x * BN;
        #pragma unroll
        for (int mt = 0; mt < 4; ++mt) {
            int r = wm * 64 + mt * 16 + grp;
            #pragma unroll
            for (int nt = 0; nt < 4; ++nt) {
                int c = wn * 32 + nt * 8 + 2 * qid;
                *(float2*)(&D[(size_t)r * Ndim + c]) =
                    make_float2(acc[mt][nt][0], acc[mt][nt][1]);
                *(float2*)(&D[(size_t)(r + 8) * Ndim + c]) =
                    make_float2(acc[mt][nt][2], acc[mt][nt][3]);
            }
        }
    }
}

extern "C" void kernel_launch(void* const* d_in, const int* in_sizes, int n_in,
                              void* d_out, int out_size) {
    const float* x  = (const float*)d_in[0];   // [8, 2048, 1024]
    const float* wi = (const float*)d_in[1];   // [8, 1024, 4096]  (= [K,N] per expert)
    const float* wo = (const float*)d_in[2];   // [8, 4096, 1024]  (= [K,N] per expert)
    float* out = (float*)d_out;                // [8, 2048, 1024] fp32

    __half *xh, *wih, *woh, *act;
    cudaGetSymbolAddress((void**)&xh,  g_xh);
    cudaGetSymbolAddress((void**)&wih, g_wih);
    cudaGetSymbolAddress((void**)&woh, g_woh);
    cudaGetSymbolAddress((void**)&act, g_act);

    cudaFuncSetAttribute(gemm_f16_w8<true>,  cudaFuncAttributeMaxDynamicSharedMemorySize, SMEM_BYTES);
    cudaFuncSetAttribute(gemm_f16_w8<false>, cudaFuncAttributeMaxDynamicSharedMemorySize, SMEM_BYTES);

    const size_t nx  = (size_t)NUM_E * M_TOK * H_DIM;
    const size_t nwi = (size_t)NUM_E * H_DIM * I_DIM;
    const size_t nwo = (size_t)NUM_E * I_DIM * H_DIM;
    cvt_f32_f16<<<1184, 256>>>(x,  xh,  nx  / 4);
    cvt_f32_f16<<<1184, 256>>>(wi, wih, nwi / 4);
    cvt_f32_f16<<<1184, 256>>>(wo, woh, nwo / 4);

    // GEMM1: act = gelu(x @ wi)   M=2048 N=4096 K=1024  (fp16 out)
    gemm_f16_w8<true><<<dim3(I_DIM / BN, M_TOK / BM, NUM_E), 256, SMEM_BYTES>>>(
        xh, wih, act, M_TOK, I_DIM, H_DIM);
    // GEMM2: out = act @ wo       M=2048 N=1024 K=4096  (fp32 out)
    gemm_f16_w8<false><<<dim3(H_DIM / BN, M_TOK / BM, NUM_E), 256, SMEM_BYTES>>>(
        act, woh, out, M_TOK, H_DIM, I_DIM);
}